// round 14
// baseline (speedup 1.0000x reference)
#include <cuda_runtime.h>
#include <cuda_fp16.h>
#include <cstdint>

// Winograd F(2x2,3x3) for: out[i,j,f] = bias[f] + sum_{a,b,c} xp[i+a, j+b, c] * g[f,c,a,b]
// where xp = x zero-padded by 3 at top/left and g = 180-flipped kernel.
// (Equivalent to the validated direct form out[i,j] = sum x[i-1-th, j-1-tw] k[th,tw].)
// M[tile,f] = sum_c V[tile,c] * U[f,c] per 4x4 position (fp16 mma.sync, fp32 accum);
// O = AT M A with compile-time {0,+1,-1} coefficients.
// R14: 512 threads / 16 warps (4m x 4n), half-size warp tiles -> low regs, 2x SMSP cover.

#define BATCH 8
#define HH 64
#define WW 64
#define CIN 64
#define FF 64

// smem map (bytes)
#define XP_OFF   0                       // 6 rows x 68 cols x 128B  = 52224
#define V_OFF    52224                   // 16 pos x 64 tiles x 128B = 131072
#define U_OFF    183296                  // 4 bufs x 64 f x 128B     = 32768
#define BIAS_OFF 216064                  // 64 floats
#define SMEM_BYTES 216320

__device__ __forceinline__ uint32_t smem_u32(const void* p) {
    uint32_t a;
    asm("{ .reg .u64 t; cvta.to.shared.u64 t, %1; cvt.u32.u64 %0, t; }" : "=r"(a) : "l"(p));
    return a;
}
__device__ __forceinline__ void ldsm4(uint32_t* r, uint32_t addr) {
    asm volatile("ldmatrix.sync.aligned.m8n8.x4.shared.b16 {%0,%1,%2,%3}, [%4];"
                 : "=r"(r[0]), "=r"(r[1]), "=r"(r[2]), "=r"(r[3]) : "r"(addr));
}
__device__ __forceinline__ void mma16(float* d, const uint32_t* a, uint32_t b0, uint32_t b1) {
    asm volatile("mma.sync.aligned.m16n8k16.row.col.f32.f16.f16.f32 "
                 "{%0,%1,%2,%3}, {%4,%5,%6,%7}, {%8,%9}, {%0,%1,%2,%3};"
                 : "+f"(d[0]), "+f"(d[1]), "+f"(d[2]), "+f"(d[3])
                 : "r"(a[0]), "r"(a[1]), "r"(a[2]), "r"(a[3]), "r"(b0), "r"(b1));
}
__device__ __forceinline__ void cp16(uint32_t dst, const void* src) {
    asm volatile("cp.async.cg.shared.global [%0], [%1], 16;"
                 :: "r"(dst), "l"(__cvta_generic_to_global(src)) : "memory");
}
#define CP_COMMIT() asm volatile("cp.async.commit_group;" ::: "memory")
#define CP_WAIT1()  asm volatile("cp.async.wait_group 1;" ::: "memory")
#define CP_WAIT0()  asm volatile("cp.async.wait_group 0;" ::: "memory")

// Transformed weights U[pos][f][c] fp16, pos = u*4+v  (8KB per position)
__device__ __half g_wu[16 * FF * CIN];

__global__ void wtrans_kernel(const float* __restrict__ kin) {
    int idx = blockIdx.x * blockDim.x + threadIdx.x;
    if (idx >= FF * CIN) return;
    int c = idx & 63, f = idx >> 6;
    float g[3][3];
    #pragma unroll
    for (int a = 0; a < 3; ++a)
        #pragma unroll
        for (int bb = 0; bb < 3; ++bb)
            g[a][bb] = kin[((f * CIN + c) * 3 + (2 - a)) * 3 + (2 - bb)];
    float T[4][3];
    #pragma unroll
    for (int j = 0; j < 3; ++j) {
        T[0][j] = g[0][j];
        T[1][j] = 0.5f * (g[0][j] + g[1][j] + g[2][j]);
        T[2][j] = 0.5f * (g[0][j] - g[1][j] + g[2][j]);
        T[3][j] = g[2][j];
    }
    #pragma unroll
    for (int u = 0; u < 4; ++u) {
        float U0 = T[u][0];
        float U1 = 0.5f * (T[u][0] + T[u][1] + T[u][2]);
        float U2 = 0.5f * (T[u][0] - T[u][1] + T[u][2]);
        float U3 = T[u][2];
        g_wu[(u * 4 + 0) * (FF * CIN) + f * CIN + c] = __float2half_rn(U0);
        g_wu[(u * 4 + 1) * (FF * CIN) + f * CIN + c] = __float2half_rn(U1);
        g_wu[(u * 4 + 2) * (FF * CIN) + f * CIN + c] = __float2half_rn(U2);
        g_wu[(u * 4 + 3) * (FF * CIN) + f * CIN + c] = __float2half_rn(U3);
    }
}

__device__ __forceinline__ float2 f2add(float2 a, float2 b) { return make_float2(a.x + b.x, a.y + b.y); }
__device__ __forceinline__ float2 f2sub(float2 a, float2 b) { return make_float2(a.x - b.x, a.y - b.y); }

__global__ __launch_bounds__(512, 1)
void conv_wino(const float* __restrict__ x,
               const float* __restrict__ bias,
               float* __restrict__ out) {
    extern __shared__ char smc[];
    const uint32_t sb  = smem_u32(smc);
    const uint32_t sbV = sb + V_OFF;
    const uint32_t sbU = sb + U_OFF;
    float* sbias = (float*)(smc + BIAS_OFF);

    const int tid = threadIdx.x;
    const int b  = blockIdx.x >> 4;
    const int r0 = blockIdx.x & 15;            // out rows 4*r0..4*r0+3, all 64 cols

    // U prefetch: 512 x 16B chunks per position (one per thread), XOR-swizzled [f][c]
    auto issueU = [&](int p) {
        uint32_t dbase = sbU + (uint32_t)((p & 3) * 8192);
        const __half* s0 = g_wu + p * (FF * CIN);
        int f  = tid >> 3, k8 = tid & 7;
        cp16(dbase + (uint32_t)(f * 128 + ((k8 ^ (f & 7)) << 4)), s0 + f * CIN + k8 * 8);
        CP_COMMIT();
    };
    issueU(0); issueU(1);

    // zero xp (covers top/left padding)
    {
        uint4 z = make_uint4(0u, 0u, 0u, 0u);
        #pragma unroll
        for (int k = 0; k < 7; ++k) {
            int idx = tid + 512 * k;
            if (idx < 52224 / 16) ((uint4*)smc)[idx] = z;
        }
        if (tid < 64) sbias[tid] = bias[tid];
    }
    __syncthreads();

    // stage xp rows 0..5 (= x rows 4*r0-3 .. 4*r0+2), cols 3..65 (= x cols 0..62), fp16
    {
        #pragma unroll
        for (int k = 0; k < 12; ++k) {
            int it = tid + 512 * k;            // 6 rows x 63 cols x 16 c4 = 6048
            if (it >= 6048) break;
            int c4   = it & 15;
            int colx = (it >> 4) % 63;
            int r    = (it >> 4) / 63;
            int gr   = 4 * r0 - 3 + r;
            if (gr < 0) continue;
            float4 v = ((const float4*)x)[((size_t)(b * HH + gr) * WW + colx) * 16 + c4];
            __half2 h0 = __float22half2_rn(make_float2(v.x, v.y));
            __half2 h1 = __float22half2_rn(make_float2(v.z, v.w));
            uint2 w;
            w.x = *(uint32_t*)&h0;
            w.y = *(uint32_t*)&h1;
            *(uint2*)(smc + (r * 68 + colx + 3) * 128 + c4 * 8) = w;
        }
    }
    __syncthreads();

    // input transform: V[u,v][tile][c] for all 16 positions (fp32 adds, one fp16 rounding)
    {
        #pragma unroll
        for (int k = 0; k < 4; ++k) {
            int it = tid + 512 * k;            // 64 tiles x 32 c2 = 2048
            int t = it >> 5, c2 = it & 31;
            int tr = t >> 5, tc = t & 31;
            const char* xb = smc + ((2 * tr) * 68 + 2 * tc) * 128 + c2 * 4;
            float2 d[4][4];
            #pragma unroll
            for (int rr = 0; rr < 4; ++rr)
                #pragma unroll
                for (int cc = 0; cc < 4; ++cc)
                    d[rr][cc] = __half22float2(*(const __half2*)(xb + (rr * 68 + cc) * 128));
            float2 F[4][4];
            #pragma unroll
            for (int cc = 0; cc < 4; ++cc) {
                F[0][cc] = f2sub(d[0][cc], d[2][cc]);
                F[1][cc] = f2add(d[1][cc], d[2][cc]);
                F[2][cc] = f2sub(d[2][cc], d[1][cc]);
                F[3][cc] = f2sub(d[1][cc], d[3][cc]);
            }
            uint32_t voff = (uint32_t)(V_OFF + t * 128 + (((c2 >> 2) ^ (t & 7)) << 4) + (c2 & 3) * 4);
            #pragma unroll
            for (int u = 0; u < 4; ++u) {
                float2 V0 = f2sub(F[u][0], F[u][2]);
                float2 V1 = f2add(F[u][1], F[u][2]);
                float2 V2 = f2sub(F[u][2], F[u][1]);
                float2 V3 = f2sub(F[u][1], F[u][3]);
                *(__half2*)(smc + voff + (u * 4 + 0) * 8192) = __float22half2_rn(V0);
                *(__half2*)(smc + voff + (u * 4 + 1) * 8192) = __float22half2_rn(V1);
                *(__half2*)(smc + voff + (u * 4 + 2) * 8192) = __float22half2_rn(V2);
                *(__half2*)(smc + voff + (u * 4 + 3) * 8192) = __float22half2_rn(V3);
            }
        }
    }

    // warp tiling: 16 warps = 4 m-groups (16 tiles) x 4 n-groups (16 f)
    const int lane = tid & 31, wid = tid >> 5;
    const int lq = lane >> 2, lr = lane & 3;
    const int wm = wid & 3;
    const int wn = wid >> 2;                   // 0..3
    const int mA = lane & 15;
    const int kc = lane >> 4;
    const int fB = (lane & 7) + 8 * ((lane >> 3) & 1);
    const int sA = mA & 7;                     // A row = 16*wm + mA
    const int sB = fB & 7;                     // B row = 16*wn + fB (16*wn mult of 8)
    const uint32_t aAbase = sbV + (uint32_t)((16 * wm + mA) * 128);
    const uint32_t aBoff  = (uint32_t)((16 * wn + fB) * 128);

    constexpr int AT0[4] = {1, 1, 1, 0};
    constexpr int AT1[4] = {0, 1, -1, -1};

    float O[2][2][2][2][2];                    // [nt][tq][fv][py][px]
    #pragma unroll
    for (int a1 = 0; a1 < 2; ++a1)
        #pragma unroll
        for (int a2 = 0; a2 < 2; ++a2)
            #pragma unroll
            for (int a3 = 0; a3 < 2; ++a3)
                #pragma unroll
                for (int a4 = 0; a4 < 2; ++a4) {
                    O[a1][a2][a3][a4][0] = 0.0f;
                    O[a1][a2][a3][a4][1] = 0.0f;
                }

    #pragma unroll
    for (int p = 0; p < 16; ++p) {
        if (p < 15) { CP_WAIT1(); } else { CP_WAIT0(); }
        __syncthreads();                       // U[p] landed; V ready (p=0); buf (p+2)&3 free
        if (p < 14) issueU(p + 2);

        float mac[2][4];
        #pragma unroll
        for (int nt = 0; nt < 2; ++nt)
            #pragma unroll
            for (int q = 0; q < 4; ++q) mac[nt][q] = 0.0f;

        const uint32_t va = aAbase + (uint32_t)(p * 8192);
        const uint32_t ub = sbU + (uint32_t)((p & 3) * 8192) + aBoff;
        #pragma unroll
        for (int ks = 0; ks < 4; ++ks) {
            const int cc = 2 * ks + kc;
            uint32_t a[4], bb[4];
            ldsm4(a,  va + ((cc ^ sA) << 4));
            ldsm4(bb, ub + ((cc ^ sB) << 4));
            mma16(mac[0], a, bb[0], bb[2]);    // f 0-7 of n16
            mma16(mac[1], a, bb[1], bb[3]);    // f 8-15
        }

        // O += AT[py][u] * AT[px][v] * M   (compile-time 0/+1/-1)
        const int u = p >> 2, v = p & 3;
        #pragma unroll
        for (int nt = 0; nt < 2; ++nt)
            #pragma unroll
            for (int j = 0; j < 4; ++j) {
                float m = mac[nt][j];
                const int tq = j >> 1, fv = j & 1;
                #pragma unroll
                for (int py = 0; py < 2; ++py) {
                    const int cy = py ? AT1[u] : AT0[u];
                    if (cy == 0) continue;
                    #pragma unroll
                    for (int px = 0; px < 2; ++px) {
                        const int cx = px ? AT1[v] : AT0[v];
                        const int c2 = cy * cx;
                        if (c2 == 0) continue;
                        if (c2 > 0) O[nt][tq][fv][py][px] += m;
                        else        O[nt][tq][fv][py][px] -= m;
                    }
                }
            }
    }

    // epilogue: bias + store (tile t = 16*wm + lq + 8*tq -> rows 4*r0+2*tr+py, col 2*tc+px)
    #pragma unroll
    for (int nt = 0; nt < 2; ++nt) {
        const int f = 16 * wn + nt * 8 + 2 * lr;
        const float b0f = sbias[f], b1f = sbias[f + 1];
        #pragma unroll
        for (int tq = 0; tq < 2; ++tq) {
            const int t = 16 * wm + lq + 8 * tq;
            const int tr = t >> 5, tc = t & 31;
            #pragma unroll
            for (int py = 0; py < 2; ++py) {
                const int i = 4 * r0 + 2 * tr + py;
                #pragma unroll
                for (int px = 0; px < 2; ++px) {
                    const int j = 2 * tc + px;
                    float2 val = make_float2(O[nt][tq][0][py][px] + b0f,
                                             O[nt][tq][1][py][px] + b1f);
                    *(float2*)(out + (((size_t)(b * HH + i) * WW + j) * FF) + f) = val;
                }
            }
        }
    }
}

extern "C" void kernel_launch(void* const* d_in, const int* in_sizes, int n_in,
                              void* d_out, int out_size) {
    const float* x    = (const float*)d_in[0];
    const float* kern = (const float*)d_in[1];
    const float* bias = (const float*)d_in[2];
    float* out = (float*)d_out;

    cudaFuncSetAttribute(conv_wino, cudaFuncAttributeMaxDynamicSharedMemorySize, SMEM_BYTES);

    wtrans_kernel<<<16, 256>>>(kern);
    conv_wino<<<BATCH * 16, 512, SMEM_BYTES>>>(x, bias, out);
}

// round 15
// speedup vs baseline: 1.1228x; 1.1228x over previous
#include <cuda_runtime.h>
#include <cuda_fp16.h>
#include <cstdint>

// Winograd F(2x2,3x3): out[i,j,f] = bias[f] + sum_{a,b,c} xp[i+a,j+b,c] * g[f,c,a,b],
// xp = x zero-padded by 3 top/left, g = 180-flipped kernel (== validated direct form).
// M[tile,f] = sum_c V[tile,c]*U[f,c] per 4x4 position (fp16 mma.sync, fp32 accum);
// O = AT M A with compile-time {0,+1,-1} coefficients.
// R15: transform reads x straight from GMEM (no xp stage, fp32 path), U 12/16 resident,
// mainloop has 3 barriers total (was 16 phase barriers).

#define BATCH 8
#define HH 64
#define WW 64
#define CIN 64
#define FF 64

// smem map (bytes): V 16x8KB | U 12x8KB | bias
#define V_OFF    0
#define U_OFF    131072
#define BIAS_OFF 229376
#define SMEM_BYTES 229632                 // <= 232448 opt-in; 1 CTA/SM

__device__ __forceinline__ uint32_t smem_u32(const void* p) {
    uint32_t a;
    asm("{ .reg .u64 t; cvta.to.shared.u64 t, %1; cvt.u32.u64 %0, t; }" : "=r"(a) : "l"(p));
    return a;
}
__device__ __forceinline__ void ldsm4(uint32_t* r, uint32_t addr) {
    asm volatile("ldmatrix.sync.aligned.m8n8.x4.shared.b16 {%0,%1,%2,%3}, [%4];"
                 : "=r"(r[0]), "=r"(r[1]), "=r"(r[2]), "=r"(r[3]) : "r"(addr));
}
__device__ __forceinline__ void mma16(float* d, const uint32_t* a, uint32_t b0, uint32_t b1) {
    asm volatile("mma.sync.aligned.m16n8k16.row.col.f32.f16.f16.f32 "
                 "{%0,%1,%2,%3}, {%4,%5,%6,%7}, {%8,%9}, {%0,%1,%2,%3};"
                 : "+f"(d[0]), "+f"(d[1]), "+f"(d[2]), "+f"(d[3])
                 : "r"(a[0]), "r"(a[1]), "r"(a[2]), "r"(a[3]), "r"(b0), "r"(b1));
}
__device__ __forceinline__ void cp16(uint32_t dst, const void* src) {
    asm volatile("cp.async.cg.shared.global [%0], [%1], 16;"
                 :: "r"(dst), "l"(__cvta_generic_to_global(src)) : "memory");
}
#define CP_COMMIT() asm volatile("cp.async.commit_group;" ::: "memory")
#define CP_WAIT0()  asm volatile("cp.async.wait_group 0;" ::: "memory")

// Transformed weights U[pos][f][c] fp16, pos = u*4+v (8KB per position)
__device__ __half g_wu[16 * FF * CIN];

__global__ void wtrans_kernel(const float* __restrict__ kin) {
    int idx = blockIdx.x * blockDim.x + threadIdx.x;
    if (idx >= FF * CIN) return;
    int c = idx & 63, f = idx >> 6;
    float g[3][3];
    #pragma unroll
    for (int a = 0; a < 3; ++a)
        #pragma unroll
        for (int bb = 0; bb < 3; ++bb)
            g[a][bb] = kin[((f * CIN + c) * 3 + (2 - a)) * 3 + (2 - bb)];
    float T[4][3];
    #pragma unroll
    for (int j = 0; j < 3; ++j) {
        T[0][j] = g[0][j];
        T[1][j] = 0.5f * (g[0][j] + g[1][j] + g[2][j]);
        T[2][j] = 0.5f * (g[0][j] - g[1][j] + g[2][j]);
        T[3][j] = g[2][j];
    }
    #pragma unroll
    for (int u = 0; u < 4; ++u) {
        float U0 = T[u][0];
        float U1 = 0.5f * (T[u][0] + T[u][1] + T[u][2]);
        float U2 = 0.5f * (T[u][0] - T[u][1] + T[u][2]);
        float U3 = T[u][2];
        g_wu[(u * 4 + 0) * (FF * CIN) + f * CIN + c] = __float2half_rn(U0);
        g_wu[(u * 4 + 1) * (FF * CIN) + f * CIN + c] = __float2half_rn(U1);
        g_wu[(u * 4 + 2) * (FF * CIN) + f * CIN + c] = __float2half_rn(U2);
        g_wu[(u * 4 + 3) * (FF * CIN) + f * CIN + c] = __float2half_rn(U3);
    }
}

__device__ __forceinline__ float2 f2add(float2 a, float2 b) { return make_float2(a.x + b.x, a.y + b.y); }
__device__ __forceinline__ float2 f2sub(float2 a, float2 b) { return make_float2(a.x - b.x, a.y - b.y); }

__global__ __launch_bounds__(512, 1)
void conv_wino(const float* __restrict__ x,
               const float* __restrict__ bias,
               float* __restrict__ out) {
    extern __shared__ char smc[];
    const uint32_t sb  = smem_u32(smc);
    const uint32_t sbV = sb + V_OFF;
    const uint32_t sbU = sb + U_OFF;
    float* sbias = (float*)(smc + BIAS_OFF);

    const int tid = threadIdx.x;
    const int lane = tid & 31, wid = tid >> 5;
    const int b  = blockIdx.x >> 4;
    const int r0 = blockIdx.x & 15;            // out rows 4*r0..4*r0+3, all 64 cols

    // ---- U positions 0..11 resident via cp.async (one 16B chunk per thread per pos) ----
    {
        const int f = tid >> 3, k8 = tid & 7;
        const uint32_t doff = (uint32_t)(f * 128 + ((k8 ^ (f & 7)) << 4));
        const __half* s0 = g_wu + f * CIN + k8 * 8;
        #pragma unroll
        for (int q = 0; q < 12; ++q)
            cp16(sbU + (uint32_t)(q * 8192) + doff, s0 + q * (FF * CIN));
        CP_COMMIT();
    }
    if (tid < 64) sbias[tid] = bias[tid];

    // ---- input transform straight from GMEM (fp32), write V for all 16 positions ----
    {
        const int c2 = lane;                   // channel pair = lane (coalesced 256B segments)
        #pragma unroll
        for (int k = 0; k < 4; ++k) {
            const int t = (tid >> 5) + 16 * k; // tile 0..63
            const int tr = t >> 5, tc = t & 31;
            float2 d[4][4];
            #pragma unroll
            for (int rr = 0; rr < 4; ++rr) {
                const int gr = 4 * r0 - 3 + 2 * tr + rr;
                #pragma unroll
                for (int cc = 0; cc < 4; ++cc) {
                    const int gc = 2 * tc - 3 + cc;
                    if (gr >= 0 && gc >= 0)
                        d[rr][cc] = *(const float2*)(x + (((size_t)(b * HH + gr) * WW) + gc) * CIN + 2 * c2);
                    else
                        d[rr][cc] = make_float2(0.f, 0.f);
                }
            }
            float2 F[4][4];
            #pragma unroll
            for (int cc = 0; cc < 4; ++cc) {
                F[0][cc] = f2sub(d[0][cc], d[2][cc]);
                F[1][cc] = f2add(d[1][cc], d[2][cc]);
                F[2][cc] = f2sub(d[2][cc], d[1][cc]);
                F[3][cc] = f2sub(d[1][cc], d[3][cc]);
            }
            const uint32_t voff = (uint32_t)(t * 128 + (((c2 >> 2) ^ (t & 7)) << 4) + (c2 & 3) * 4);
            #pragma unroll
            for (int u = 0; u < 4; ++u) {
                float2 V0 = f2sub(F[u][0], F[u][2]);
                float2 V1 = f2add(F[u][1], F[u][2]);
                float2 V2 = f2sub(F[u][2], F[u][1]);
                float2 V3 = f2sub(F[u][1], F[u][3]);
                *(__half2*)(smc + V_OFF + voff + (u * 4 + 0) * 8192) = __float22half2_rn(V0);
                *(__half2*)(smc + V_OFF + voff + (u * 4 + 1) * 8192) = __float22half2_rn(V1);
                *(__half2*)(smc + V_OFF + voff + (u * 4 + 2) * 8192) = __float22half2_rn(V2);
                *(__half2*)(smc + V_OFF + voff + (u * 4 + 3) * 8192) = __float22half2_rn(V3);
            }
        }
    }

    CP_WAIT0();
    __syncthreads();                           // barrier 1: V complete + U0..11 landed

    // ---- warp tiling: 16 warps = 4 m-groups (16 tiles) x 4 n-groups (16 f) ----
    const int lq = lane >> 2, lr = lane & 3;
    const int wm = wid & 3;
    const int wn = wid >> 2;
    const int mA = lane & 15;
    const int kc = lane >> 4;
    const int fB = (lane & 7) + 8 * ((lane >> 3) & 1);
    const int sA = mA & 7;
    const int sB = fB & 7;
    const uint32_t aAbase = sbV + (uint32_t)((16 * wm + mA) * 128);
    const uint32_t aBoff  = (uint32_t)((16 * wn + fB) * 128);

    constexpr int AT0[4] = {1, 1, 1, 0};
    constexpr int AT1[4] = {0, 1, -1, -1};

    float O[2][2][2][2][2];                    // [nt][tq][fv][py][px]
    #pragma unroll
    for (int a1 = 0; a1 < 2; ++a1)
        #pragma unroll
        for (int a2 = 0; a2 < 2; ++a2)
            #pragma unroll
            for (int a3 = 0; a3 < 2; ++a3)
                #pragma unroll
                for (int a4 = 0; a4 < 2; ++a4) {
                    O[a1][a2][a3][a4][0] = 0.0f;
                    O[a1][a2][a3][a4][1] = 0.0f;
                }

    auto do_phase = [&](int p, int slot) {
        float mac[2][4];
        #pragma unroll
        for (int nt = 0; nt < 2; ++nt)
            #pragma unroll
            for (int q = 0; q < 4; ++q) mac[nt][q] = 0.0f;

        const uint32_t va = aAbase + (uint32_t)(p * 8192);
        const uint32_t ub = sbU + (uint32_t)(slot * 8192) + aBoff;
        #pragma unroll
        for (int ks = 0; ks < 4; ++ks) {
            const int cc = 2 * ks + kc;
            uint32_t a[4], bb[4];
            ldsm4(a,  va + ((cc ^ sA) << 4));
            ldsm4(bb, ub + ((cc ^ sB) << 4));
            mma16(mac[0], a, bb[0], bb[2]);
            mma16(mac[1], a, bb[1], bb[3]);
        }

        const int u = p >> 2, v = p & 3;
        #pragma unroll
        for (int nt = 0; nt < 2; ++nt)
            #pragma unroll
            for (int j = 0; j < 4; ++j) {
                float m = mac[nt][j];
                const int tq = j >> 1, fv = j & 1;
                #pragma unroll
                for (int py = 0; py < 2; ++py) {
                    const int cy = py ? AT1[u] : AT0[u];
                    if (cy == 0) continue;
                    #pragma unroll
                    for (int px = 0; px < 2; ++px) {
                        const int cx = px ? AT1[v] : AT0[v];
                        const int c2 = cy * cx;
                        if (c2 == 0) continue;
                        if (c2 > 0) O[nt][tq][fv][py][px] += m;
                        else        O[nt][tq][fv][py][px] -= m;
                    }
                }
            }
    };

    // phases 0-7 barrier-free
    #pragma unroll
    for (int p = 0; p < 8; ++p) do_phase(p, p);

    __syncthreads();                           // barrier 2: U slots 0-3 fully consumed
    {   // refill slots 0-3 with positions 12-15 (overlaps phases 8-11)
        const int f = tid >> 3, k8 = tid & 7;
        const uint32_t doff = (uint32_t)(f * 128 + ((k8 ^ (f & 7)) << 4));
        const __half* s0 = g_wu + f * CIN + k8 * 8;
        #pragma unroll
        for (int q = 12; q < 16; ++q)
            cp16(sbU + (uint32_t)((q - 12) * 8192) + doff, s0 + q * (FF * CIN));
        CP_COMMIT();
    }

    #pragma unroll
    for (int p = 8; p < 12; ++p) do_phase(p, p);

    CP_WAIT0();
    __syncthreads();                           // barrier 3: positions 12-15 landed

    #pragma unroll
    for (int p = 12; p < 16; ++p) do_phase(p, p - 12);

    // ---- epilogue: bias + store ----
    #pragma unroll
    for (int nt = 0; nt < 2; ++nt) {
        const int f = 16 * wn + nt * 8 + 2 * lr;
        const float b0f = sbias[f], b1f = sbias[f + 1];
        #pragma unroll
        for (int tq = 0; tq < 2; ++tq) {
            const int t = 16 * wm + lq + 8 * tq;
            const int tr = t >> 5, tc = t & 31;
            #pragma unroll
            for (int py = 0; py < 2; ++py) {
                const int i = 4 * r0 + 2 * tr + py;
                #pragma unroll
                for (int px = 0; px < 2; ++px) {
                    const int j = 2 * tc + px;
                    float2 val = make_float2(O[nt][tq][0][py][px] + b0f,
                                             O[nt][tq][1][py][px] + b1f);
                    *(float2*)(out + (((size_t)(b * HH + i) * WW + j) * FF) + f) = val;
                }
            }
        }
    }
}

extern "C" void kernel_launch(void* const* d_in, const int* in_sizes, int n_in,
                              void* d_out, int out_size) {
    const float* x    = (const float*)d_in[0];
    const float* kern = (const float*)d_in[1];
    const float* bias = (const float*)d_in[2];
    float* out = (float*)d_out;

    cudaFuncSetAttribute(conv_wino, cudaFuncAttributeMaxDynamicSharedMemorySize, SMEM_BYTES);

    wtrans_kernel<<<16, 256>>>(kern);
    conv_wino<<<BATCH * 16, 512, SMEM_BYTES>>>(x, bias, out);
}